// round 12
// baseline (speedup 1.0000x reference)
#include <cuda_runtime.h>
#include <cstdint>

// Problem: input (512, 2048, 7, 7) fp32 -> per row of 49: mean of top-4.
// Output: (512, 2048, 1, 1) = 1,048,576 floats.
//
// R11: persistent warps, per-warp 2-deep DMA ring. One wave (4 CTAs/SM x
// 128 thr); each warp owns two 32-row chunk buffers (2 x 6,272 B) and two
// private mbarriers, and loops over chunks strided by the total warp count:
//   pre-issue buf0,buf1;  loop { wait(buf); compute 32 rows; store;
//                                issue next chunk into buf; }
// DMA for the next chunk is always in flight during compute (true per-warp
// copy/compute overlap), with zero cross-warp coupling, no CTA churn and
// no wave transitions. Top-4 math = measured-best linear sort4+merge4.

#define THREADS      128
#define WARPS_CTA    4
#define CHUNK_ROWS   32
#define ROW_LEN      49
#define CHUNK_FLOATS (CHUNK_ROWS * ROW_LEN)   // 1568
#define CHUNK_BYTES  (CHUNK_FLOATS * 4)       // 6272
#define CTAS_PER_SM  4

__device__ __forceinline__ void ce(float& x, float& y) {
    float hi = fmaxf(x, y);
    float lo = fminf(x, y);
    x = hi; y = lo;
}

__device__ __forceinline__ void sort4(float& a, float& b, float& c, float& d) {
    ce(a, b); ce(c, d); ce(a, c); ce(b, d); ce(b, c);
}

__device__ __forceinline__ void merge4(float& t0, float& t1, float& t2, float& t3,
                                       float c0, float c1, float c2, float c3) {
    float m0 = fmaxf(t0, c3);
    float m1 = fmaxf(t1, c2);
    float m2 = fmaxf(t2, c1);
    float m3 = fmaxf(t3, c0);
    ce(m0, m2); ce(m1, m3); ce(m0, m1); ce(m2, m3);
    t0 = m0; t1 = m1; t2 = m2; t3 = m3;
}

__device__ __forceinline__ void mbar_init(uint32_t a, uint32_t cnt) {
    asm volatile("mbarrier.init.shared.b64 [%0], %1;" :: "r"(a), "r"(cnt) : "memory");
}

__device__ __forceinline__ void mbar_expect_tx(uint32_t a, uint32_t bytes) {
    asm volatile("mbarrier.arrive.expect_tx.shared.b64 _, [%0], %1;"
                 :: "r"(a), "r"(bytes) : "memory");
}

__device__ __forceinline__ void mbar_wait(uint32_t a, uint32_t parity) {
    asm volatile(
        "{\n\t"
        ".reg .pred p;\n\t"
        "WAIT_%=:\n\t"
        "mbarrier.try_wait.parity.shared.b64 p, [%0], %1;\n\t"
        "@!p bra WAIT_%=;\n\t"
        "}"
        :: "r"(a), "r"(parity) : "memory");
}

__device__ __forceinline__ void bulk_copy(uint32_t smem_dst, const void* gmem_src,
                                          uint32_t bytes, uint32_t mbar) {
    asm volatile(
        "cp.async.bulk.shared::cta.global.mbarrier::complete_tx::bytes "
        "[%0], [%1], %2, [%3];"
        :: "r"(smem_dst), "l"(gmem_src), "r"(bytes), "r"(mbar) : "memory");
}

__global__ __launch_bounds__(THREADS)
void apool_topk4_kernel(const float* __restrict__ in, float* __restrict__ out,
                        int nchunks) {
    extern __shared__ float s[];   // WARPS_CTA * 2 * CHUNK_FLOATS
    __shared__ __align__(8) uint64_t mbar_s[WARPS_CTA * 2];

    const int tid  = threadIdx.x;
    const int wid  = tid >> 5;
    const int lane = tid & 31;

    // warp-private smem: two chunk buffers back to back
    float* wbase = s + wid * (2 * CHUNK_FLOATS);
    const uint32_t w_s = (uint32_t)__cvta_generic_to_shared(wbase);
    const uint32_t mb0 = (uint32_t)__cvta_generic_to_shared(&mbar_s[wid * 2]);
    const uint32_t mb1 = mb0 + 8u;

    const int W = gridDim.x * WARPS_CTA;           // total warps
    const int wgid = blockIdx.x * WARPS_CTA + wid; // this warp's id

    // ---- Init both barriers, pre-issue chunks j=0 (buf0) and j=1 (buf1) ----
    if (lane == 0) {
        mbar_init(mb0, 1);
        mbar_init(mb1, 1);
        asm volatile("fence.proxy.async.shared::cta;" ::: "memory");
        long long c0 = wgid;                 // chunk for j=0
        long long c1 = wgid + (long long)W;  // chunk for j=1
        if (c0 < nchunks) {
            mbar_expect_tx(mb0, CHUNK_BYTES);
            bulk_copy(w_s, in + c0 * CHUNK_FLOATS, CHUNK_BYTES, mb0);
        }
        if (c1 < nchunks) {
            mbar_expect_tx(mb1, CHUNK_BYTES);
            bulk_copy(w_s + CHUNK_BYTES, in + c1 * CHUNK_FLOATS, CHUNK_BYTES, mb1);
        }
    }
    __syncwarp();

    // ---- Main loop: wait slot, compute, store, refill slot ----
    for (int j = 0; ; j++) {
        const long long cid = (long long)wgid + (long long)j * W;
        if (cid >= nchunks) break;

        const int slot = j & 1;
        const uint32_t par = (uint32_t)(j >> 1) & 1u;
        const uint32_t mb = slot ? mb1 : mb0;

        mbar_wait(mb, par);

        const float* row = wbase + slot * CHUNK_FLOATS + lane * ROW_LEN;

        float t0 = row[0], t1 = row[1], t2 = row[2], t3 = row[3];
        sort4(t0, t1, t2, t3);
        #pragma unroll
        for (int k = 1; k < 12; k++) {
            float c0 = row[4 * k + 0];
            float c1 = row[4 * k + 1];
            float c2 = row[4 * k + 2];
            float c3 = row[4 * k + 3];
            sort4(c0, c1, c2, c3);
            merge4(t0, t1, t2, t3, c0, c1, c2, c3);
        }
        float e = row[48];
        t3 = fmaxf(t3, e);
        ce(t2, t3); ce(t1, t2); ce(t0, t1);

        out[cid * CHUNK_ROWS + lane] = (t0 + t1 + t2 + t3) * 0.25f;

        // refill this slot with chunk j+2 (all lanes done reading: the alu
        // ops above consumed every LDS result in program order)
        __syncwarp();
        if (lane == 0) {
            const long long cn = cid + 2LL * W;
            if (cn < nchunks) {
                mbar_expect_tx(mb, CHUNK_BYTES);
                bulk_copy(w_s + (uint32_t)slot * CHUNK_BYTES,
                          in + cn * CHUNK_FLOATS, CHUNK_BYTES, mb);
            }
        }
    }
}

extern "C" void kernel_launch(void* const* d_in, const int* in_sizes, int n_in,
                              void* d_out, int out_size) {
    const float* in = (const float*)d_in[0];
    float* out = (float*)d_out;

    int dev = 0, sms = 148;
    cudaGetDevice(&dev);
    cudaDeviceGetAttribute(&sms, cudaDevAttrMultiProcessorCount, dev);

    const int rows = out_size;                 // 1,048,576
    const int nchunks = rows / CHUNK_ROWS;     // 32,768
    const int blocks = sms * CTAS_PER_SM;      // one resident wave
    const int smem = WARPS_CTA * 2 * CHUNK_BYTES;  // 50,176 B -> 4 CTAs/SM

    cudaFuncSetAttribute(apool_topk4_kernel,
                         cudaFuncAttributeMaxDynamicSharedMemorySize, smem);
    apool_topk4_kernel<<<blocks, THREADS, smem>>>(in, out, nchunks);
}

// round 13
// speedup vs baseline: 1.0999x; 1.0999x over previous
#include <cuda_runtime.h>
#include <cstdint>

// Problem: input (512, 2048, 7, 7) fp32 -> per row of 49: mean of top-4.
// Output: (512, 2048, 1, 1) = 1,048,576 floats.
//
// R12: one WARP per CTA. 32,768 CTAs x 32 threads, smem = one 32-row chunk
// (6,272 B) -> HW limit 32 CTAs/SM = ~32 fully independent single-warp
// pipelines per SM. Each CTA: lane 0 inits its mbarrier, fences, issues one
// cp.async.bulk; warp waits, computes one row per lane (sort4 + bitonic
// merge4), stores coalesced, exits. CTA scheduler backfills retiring warps
// one at a time -> no multi-warp drain bubbles (R10's residual), keeping a
// continuous stream of DMA issues per SM.

#define THREADS      32
#define CHUNK_ROWS   32
#define ROW_LEN      49
#define CHUNK_FLOATS (CHUNK_ROWS * ROW_LEN)   // 1568
#define CHUNK_BYTES  (CHUNK_FLOATS * 4)       // 6272

__device__ __forceinline__ void ce(float& x, float& y) {
    float hi = fmaxf(x, y);
    float lo = fminf(x, y);
    x = hi; y = lo;
}

__device__ __forceinline__ void sort4(float& a, float& b, float& c, float& d) {
    ce(a, b); ce(c, d); ce(a, c); ce(b, d); ce(b, c);
}

__device__ __forceinline__ void merge4(float& t0, float& t1, float& t2, float& t3,
                                       float c0, float c1, float c2, float c3) {
    float m0 = fmaxf(t0, c3);
    float m1 = fmaxf(t1, c2);
    float m2 = fmaxf(t2, c1);
    float m3 = fmaxf(t3, c0);
    ce(m0, m2); ce(m1, m3); ce(m0, m1); ce(m2, m3);
    t0 = m0; t1 = m1; t2 = m2; t3 = m3;
}

__device__ __forceinline__ void mbar_init(uint32_t a, uint32_t cnt) {
    asm volatile("mbarrier.init.shared.b64 [%0], %1;" :: "r"(a), "r"(cnt) : "memory");
}

__device__ __forceinline__ void mbar_expect_tx(uint32_t a, uint32_t bytes) {
    asm volatile("mbarrier.arrive.expect_tx.shared.b64 _, [%0], %1;"
                 :: "r"(a), "r"(bytes) : "memory");
}

__device__ __forceinline__ void mbar_wait(uint32_t a, uint32_t parity) {
    asm volatile(
        "{\n\t"
        ".reg .pred p;\n\t"
        "WAIT_%=:\n\t"
        "mbarrier.try_wait.parity.shared.b64 p, [%0], %1;\n\t"
        "@!p bra WAIT_%=;\n\t"
        "}"
        :: "r"(a), "r"(parity) : "memory");
}

__device__ __forceinline__ void bulk_copy(uint32_t smem_dst, const void* gmem_src,
                                          uint32_t bytes, uint32_t mbar) {
    asm volatile(
        "cp.async.bulk.shared::cta.global.mbarrier::complete_tx::bytes "
        "[%0], [%1], %2, [%3];"
        :: "r"(smem_dst), "l"(gmem_src), "r"(bytes), "r"(mbar) : "memory");
}

__global__ __launch_bounds__(THREADS)
void apool_topk4_kernel(const float* __restrict__ in, float* __restrict__ out) {
    extern __shared__ float s[];                 // CHUNK_FLOATS
    __shared__ __align__(8) uint64_t mbar_s;

    const int lane = threadIdx.x;
    const uint32_t s_base = (uint32_t)__cvta_generic_to_shared(s);
    const uint32_t mb     = (uint32_t)__cvta_generic_to_shared(&mbar_s);
    const long long cid = blockIdx.x;            // chunk id

    // ---- Issue this chunk's DMA immediately ----
    if (lane == 0) {
        mbar_init(mb, 1);
        asm volatile("fence.proxy.async.shared::cta;" ::: "memory");
        mbar_expect_tx(mb, CHUNK_BYTES);
        bulk_copy(s_base, in + cid * CHUNK_FLOATS, CHUNK_BYTES, mb);
    }
    __syncwarp();
    mbar_wait(mb, 0);

    // ---- Compute: one row per lane (stride 49 -> conflict-free) ----
    const float* row = s + lane * ROW_LEN;

    float t0 = row[0], t1 = row[1], t2 = row[2], t3 = row[3];
    sort4(t0, t1, t2, t3);

    #pragma unroll
    for (int k = 1; k < 12; k++) {
        float c0 = row[4 * k + 0];
        float c1 = row[4 * k + 1];
        float c2 = row[4 * k + 2];
        float c3 = row[4 * k + 3];
        sort4(c0, c1, c2, c3);
        merge4(t0, t1, t2, t3, c0, c1, c2, c3);
    }
    float e = row[48];
    t3 = fmaxf(t3, e);
    ce(t2, t3); ce(t1, t2); ce(t0, t1);

    out[cid * CHUNK_ROWS + lane] = (t0 + t1 + t2 + t3) * 0.25f;
}

extern "C" void kernel_launch(void* const* d_in, const int* in_sizes, int n_in,
                              void* d_out, int out_size) {
    const float* in = (const float*)d_in[0];
    float* out = (float*)d_out;

    const int rows = out_size;                 // 1,048,576
    const int blocks = rows / CHUNK_ROWS;      // 32,768, divides exactly
    const int smem = CHUNK_BYTES;              // 6,272 B -> 32 CTAs/SM (HW cap)

    cudaFuncSetAttribute(apool_topk4_kernel,
                         cudaFuncAttributeMaxDynamicSharedMemorySize, smem);
    apool_topk4_kernel<<<blocks, THREADS, smem>>>(in, out);
}